// round 12
// baseline (speedup 1.0000x reference)
#include <cuda_runtime.h>
#include <math.h>
#include <stdint.h>

// ---------------- problem constants (IMG 800x1024, strides 8..128) ----------
#define NBATCH 16
#define NCLS   80
#define TOPN   300
#define KC     1504
#define NREAL  1500
#define NWORDS 47
#define POST   100
#define CAP    4096
#define NBLK_A 740            // 148 SMs x 5 resident blocks (guaranteed)

__constant__ int c_HW[5]   = {12800, 3200, 800, 208, 56};
__constant__ int c_CHW[5]  = {1024000, 256000, 64000, 16640, 4480};
__constant__ int c_LOFF[5] = {0, 204800, 256000, 268800, 272128};
__constant__ int c_R[5]    = {40, 80, 300, 300, 300};
__constant__ int c_BPP[5]  = {250, 63, 16, 5, 2};
__constant__ int c_BOFF[5] = {0, 4000, 5008, 5264, 5344};
#define NCHUNKS 5376
#define SCTR_TOTAL 273024

// ---------------- device scratch (static, allocation-free) ------------------
__device__ float    g_sctr[SCTR_TOTAL];
__device__ float    g_L[SCTR_TOTAL];
__device__ unsigned g_hist1[80 * 2048];
__device__ unsigned g_scnt[80];
__device__ unsigned long long g_surv[(size_t)80 * CAP];
__device__ unsigned long long g_ckey[NBATCH * KC];   // (score ‖ ~(l<<20|idx)); 0=invalid
__device__ float    g_cscore[NBATCH * KC];
__device__ float4   g_cbox4[NBATCH * KC];
__device__ int      g_clabel[NBATCH * KC];
// software grid barrier (replay-safe: generation monotonic, arrive self-resets)
__device__ volatile unsigned g_gen;
__device__ unsigned g_arrive;

struct InPtrs {
    const float* loc[5];
    const float* cls[5];
    const float* box[5];
    const float* ctr[5];
};

__device__ __forceinline__ float sigm(float x) { return 1.0f / (1.0f + expf(-x)); }

__device__ __forceinline__ float approx_rcp(float d) {
    float r = __int_as_float(0x7EF311C3 - __float_as_int(d));
    r = r * (2.0f - d * r);
    r = r * (2.0f - d * r);
    return r;
}
__device__ __forceinline__ float approx_a(float cv, float sv) {
    float t = fminf(cv, 60.0f) * -1.44269504f;
    float fl = floorf(t);
    float f = t - fl;
    float p2 = fmaf(fmaf(0.33718944f, f, 0.65763628f), f, 1.0017247f);
    float z = p2 * __int_as_float(((int)fl + 127) << 23);
    return approx_rcp(1.0f + z) * sv;
}

__device__ __forceinline__ void map_block(int bid, int& l, int& b, int& chunk) {
    if (bid < 4000)      l = 0;
    else if (bid < 5008) l = 1;
    else if (bid < 5264) l = 2;
    else if (bid < 5344) l = 3;
    else                 l = 4;
    int rel = bid - c_BOFF[l];
    b = rel / c_BPP[l];
    chunk = rel % c_BPP[l];
}

__device__ __forceinline__ void grid_sync() {
    __syncthreads();
    if (threadIdx.x == 0) {
        __threadfence();
        unsigned gen = g_gen;
        if (atomicAdd(&g_arrive, 1u) == NBLK_A - 1) {
            g_arrive = 0;
            __threadfence();
            g_gen = gen + 1;
        } else {
            while (g_gen == gen) { __nanosleep(32); }
        }
        __threadfence();
    }
    __syncthreads();
}

// R6-proven collect body (float4, 4096-elem chunk)
template <int HW>
__device__ __forceinline__ void collect_body(const float4* cls4, const float4* Lv,
                                             const float* sctr, int start, int chw, int p) {
    int e4end = min(start + 4096, chw) >> 2;
    for (int e4 = (start >> 2) + threadIdx.x; e4 < e4end; e4 += 256) {
        float4 v = cls4[e4];
        int e = e4 << 2;
        int c0 = e / HW;
        int pos0 = e - c0 * HW;
        float4 L4 = Lv[pos0 >> 2];
        float vv[4] = {v.x, v.y, v.z, v.w};
        float LL[4] = {L4.x, L4.y, L4.z, L4.w};
        #pragma unroll
        for (int k = 0; k < 4; k++) {
            float cv = vv[k];
            if (cv < LL[k]) continue;
            float se = sigm(cv);              // rare exact path (reference rounding)
            if (se <= 0.05f) continue;
            float sv = sctr[pos0 + k];
            float m = se * sv;
            unsigned key32 = __float_as_uint(m) | 0x80000000u;
            unsigned idx = (unsigned)((pos0 + k) * NCLS + c0);
            unsigned long long key = ((unsigned long long)key32 << 32) | (unsigned)(~idx);
            unsigned slot = atomicAdd(&g_scnt[p], 1u);
            if (slot < CAP) g_surv[(size_t)p * CAP + slot] = key;
        }
    }
}

// decode one accepted candidate into slot s of pair (l,b)  [R9-proven]
__device__ __forceinline__ void write_candidate(int l, int b, int s, unsigned long long key,
                                                const float* bx, const float* loc, int hw) {
    unsigned hi = (unsigned)(key >> 32);
    float m = __uint_as_float(hi ^ 0x80000000u);
    unsigned idx = ~(unsigned)(key & 0xFFFFFFFFu);
    int pos = (int)(idx / NCLS), c = (int)(idx % NCLS);
    float bl = bx[pos], bt = bx[hw + pos], br = bx[2 * hw + pos], bbo = bx[3 * hw + pos];
    float lx = loc[2 * pos], ly = loc[2 * pos + 1];
    float x1 = fminf(fmaxf(lx - bl, 0.f), 1023.f);
    float y1 = fminf(fmaxf(ly - bt, 0.f), 799.f);
    float x2 = fminf(fmaxf(lx + br, 0.f), 1023.f);
    float y2 = fminf(fmaxf(ly + bbo, 0.f), 799.f);
    int ci = b * KC + l * TOPN + s;
    g_cscore[ci] = sqrtf(fmaxf(m, 1e-12f));
    g_cbox4[ci] = make_float4(x1, y1, x2, y2);
    g_clabel[ci] = c + 1;
    g_ckey[ci] = ((unsigned long long)hi << 32) |
                 (unsigned)(~(((unsigned)l << 20) | idx));
}

// score-bin for select: ~1024 used bins over score in [0.0625, 1], monotone
__device__ __forceinline__ int sbin(unsigned hi) {
    int d = (int)(hi - 0xBD800000u) >> 15;
    return min(2047, max(d, 0));
}

// ================== kernel A: persistent fused pipeline ======================
__global__ __launch_bounds__(256, 5) void k_mega(InPtrs P) {
    __shared__ __align__(16) unsigned char s_u[25600]; // hist 8K | part 1K | ties 16K
    __shared__ float s_thr;
    __shared__ int s_B, s_nacc, s_ntie;
    int bid = blockIdx.x, t = threadIdx.x;
    int gtid = bid * 256 + t;

    // ---- P0: zero scratch + exact sigmoid(ctr) ----
    for (int i = gtid; i < 80 * 2048; i += NBLK_A * 256) g_hist1[i] = 0;
    if (gtid < 80) g_scnt[gtid] = 0;
    for (int i = gtid; i < SCTR_TOTAL; i += NBLK_A * 256) {
        int l = (i < 204800) ? 0 : (i < 256000) ? 1 : (i < 268800) ? 2 : (i < 272128) ? 3 : 4;
        g_sctr[i] = sigm(P.ctr[l][i - c_LOFF[l]]);
    }
    grid_sync();

    // ---- P1: sampled approx-score histogram (blocks 0..207) [R6-proven] ----
    if (bid < 208) {
        unsigned* hist = (unsigned*)s_u;
        for (int i = t; i < 2048; i += 256) hist[i] = 0;
        __syncthreads();
        int l, b, sub, nsub, stride;
        if (bid < 128)      { l = 0; b = bid >> 3; sub = bid & 7; nsub = 8; stride = 32; }
        else if (bid < 160) { l = 1; b = (bid - 128) >> 1; sub = (bid - 128) & 1; nsub = 2; stride = 8; }
        else if (bid < 176) { l = 2; b = bid - 160; sub = 0; nsub = 1; stride = 1; }
        else if (bid < 192) { l = 3; b = bid - 176; sub = 0; nsub = 1; stride = 1; }
        else                { l = 4; b = bid - 192; sub = 0; nsub = 1; stride = 1; }
        int chw4 = c_CHW[l] >> 2;
        int per = chw4 / nsub;
        int hw = c_HW[l];
        const float4* cls4 = (const float4*)(P.cls[l]) + (size_t)b * chw4 + (size_t)sub * per;
        const float4* sctr4 = (const float4*)(g_sctr + c_LOFF[l] + b * hw);
        int base_e = sub * per * 4;
        for (int i4 = t * stride; i4 < per; i4 += 256 * stride) {
            float4 v = cls4[i4];
            int e = base_e + (i4 << 2);
            int pos0 = e % hw;
            float4 s4 = sctr4[pos0 >> 2];
            float vv[4] = {v.x, v.y, v.z, v.w};
            float ss[4] = {s4.x, s4.y, s4.z, s4.w};
            #pragma unroll
            for (int k = 0; k < 4; k++) {
                float cv = vv[k];
                if (cv < -2.945f) continue;
                float a = approx_a(cv, ss[k]);
                atomicAdd(&hist[min(2047, (int)(a * 2048.0f))], 1u);
            }
        }
        __syncthreads();
        int p = l * 16 + b;
        for (int i = t; i < 2048; i += 256)
            if (hist[i]) atomicAdd(&g_hist1[p * 2048 + i], hist[i]);
    }
    grid_sync();

    // ---- P2: threshold -> per-position logit L (blocks 0..79) [R6-proven] ----
    if (bid < 80) {
        unsigned* sh = (unsigned*)s_u;
        unsigned* part = (unsigned*)(s_u + 8192);
        int p = bid;
        if (t == 0) s_thr = 0.0f;
        unsigned R = (unsigned)c_R[p / 16];
        const unsigned* h = g_hist1 + (size_t)p * 2048;
        unsigned lsum = 0;
        for (int i = 0; i < 8; i++) { unsigned v = h[t * 8 + i]; sh[t * 8 + i] = v; lsum += v; }
        part[t] = lsum;
        __syncthreads();
        for (int off = 1; off < 256; off <<= 1) {
            unsigned o = (t + off < 256) ? part[t + off] : 0u;
            __syncthreads();
            part[t] += o;
            __syncthreads();
        }
        unsigned cum = (t < 255) ? part[t + 1] : 0u;
        for (int i = 7; i >= 0; i--) {
            int bidx = t * 8 + i;
            unsigned hv = sh[bidx];
            if (cum < R && cum + hv >= R)
                s_thr = (float)bidx * (1.0f / 2048.0f) * 0.985f;
            cum += hv;
        }
        __syncthreads();
        float thr = s_thr;
        int l = p / 16, b = p % 16;
        int hw = c_HW[l];
        int base = c_LOFF[l] + b * hw;
        for (int i = t; i < hw; i += 256) {
            float sv = g_sctr[base + i];
            float L;
            if (thr <= 0.0f) L = -2.944f;
            else {
                float x = thr / sv;
                if (x >= 1.0f) L = 1e30f;
                else L = fmaxf(logf(x / (1.0f - x)) - 0.02f, -2.944f);
            }
            g_L[base + i] = L;
        }
    }
    grid_sync();

    // ---- P3: full sweep, multi-chunk per block [R6 body] ----
    for (int c = bid; c < NCHUNKS; c += NBLK_A) {
        int l, b, chunk; map_block(c, l, b, chunk);
        int p = l * 16 + b;
        int start = chunk * 4096;
        switch (l) {
        case 0: collect_body<12800>((const float4*)(P.cls[0] + (size_t)b * 1024000),
                (const float4*)(g_L + 0 + b * 12800), g_sctr + 0 + b * 12800, start, 1024000, p); break;
        case 1: collect_body<3200>((const float4*)(P.cls[1] + (size_t)b * 256000),
                (const float4*)(g_L + 204800 + b * 3200), g_sctr + 204800 + b * 3200, start, 256000, p); break;
        case 2: collect_body<800>((const float4*)(P.cls[2] + (size_t)b * 64000),
                (const float4*)(g_L + 256000 + b * 800), g_sctr + 256000 + b * 800, start, 64000, p); break;
        case 3: collect_body<208>((const float4*)(P.cls[3] + (size_t)b * 16640),
                (const float4*)(g_L + 268800 + b * 208), g_sctr + 268800 + b * 208, start, 16640, p); break;
        case 4: collect_body<56>((const float4*)(P.cls[4] + (size_t)b * 4480),
                (const float4*)(g_L + 272128 + b * 56), g_sctr + 272128 + b * 56, start, 4480, p); break;
        }
    }
    grid_sync();

    // ---- P4: exact top-300 SET via radix select (blocks 0..79) ----
    if (bid < 80) {
        unsigned* hist = (unsigned*)s_u;
        unsigned* part = (unsigned*)(s_u + 8192);
        unsigned long long* ties = (unsigned long long*)(s_u + 9216);
        int p = bid, l = p / 16, b = p % 16;
        int n = min((int)g_scnt[p], CAP);
        const unsigned long long* sv = g_surv + (size_t)p * CAP;
        int hw = c_HW[l];
        const float* bx = P.box[l] + (size_t)b * 4 * hw;
        const float* loc = P.loc[l];
        if (t == 0) { s_nacc = 0; s_ntie = 0; s_B = 0; }
        int B = -1;                        // n<=300: accept all
        if (n > TOPN) {
            for (int i = t; i < 2048; i += 256) hist[i] = 0;
            __syncthreads();
            for (int i = t; i < n; i += 256)
                atomicAdd(&hist[sbin((unsigned)(sv[i] >> 32))], 1u);
            __syncthreads();
            unsigned lsum = 0;
            #pragma unroll
            for (int k = 0; k < 8; k++) lsum += hist[t * 8 + k];
            part[t] = lsum;
            __syncthreads();
            for (int off = 1; off < 256; off <<= 1) {  // suffix sums
                unsigned o = (t + off < 256) ? part[t + off] : 0u;
                __syncthreads();
                part[t] += o;
                __syncthreads();
            }
            unsigned cum = (t < 255) ? part[t + 1] : 0u;
            for (int k = 7; k >= 0; k--) {
                int bidx = t * 8 + k;
                unsigned hv = hist[bidx];
                if (cum < TOPN && cum + hv >= TOPN) s_B = bidx;
                cum += hv;
            }
            __syncthreads();
            B = s_B;
        } else {
            __syncthreads();
        }
        for (int i = t; i < n; i += 256) {
            unsigned long long key = sv[i];
            int bin = sbin((unsigned)(key >> 32));
            if (bin > B) {
                int s = atomicAdd(&s_nacc, 1);
                write_candidate(l, b, s, key, bx, loc, hw);
            } else if (bin == B) {
                int s = atomicAdd(&s_ntie, 1);
                if (s < 2048) ties[s] = key;
            }
        }
        __syncthreads();
        int nacc = s_nacc;
        int total = nacc;
        if (n > TOPN) {
            int take = TOPN - nacc;
            int ntie = min(s_ntie, 2048);
            int P2 = 32; while (P2 < ntie) P2 <<= 1;
            for (int i = t; i < P2; i += 256) if (i >= ntie) ties[i] = 0ull;
            __syncthreads();
            for (int k2 = 2; k2 <= P2; k2 <<= 1)
                for (int j = k2 >> 1; j > 0; j >>= 1) {
                    for (int i = t; i < P2; i += 256) {
                        int ix = i ^ j;
                        if (ix > i) {
                            bool up = ((i & k2) == 0);
                            unsigned long long a = ties[i], cc = ties[ix];
                            if (up ? (a < cc) : (a > cc)) { ties[i] = cc; ties[ix] = a; }
                        }
                    }
                    __syncthreads();
                }
            for (int i = t; i < take; i += 256)
                write_candidate(l, b, nacc + i, ties[i], bx, loc, hw);
            total = TOPN;
        }
        for (int s = total + t; s < TOPN; s += 256)
            g_ckey[b * KC + l * TOPN + s] = 0ull;      // replay-safe invalid
    }
}

// ================== kernel B: fused per-image sort + NMS + emit [R9-proven] ==
__global__ __launch_bounds__(1024) void k_final(float* out) {
    __shared__ __align__(16) unsigned char s_raw[24576];   // skey16K+spay4K | sb 23.5K
    __shared__ float sa[KC];
    __shared__ float ssc[KC];
    __shared__ unsigned short sslot[KC];
    __shared__ unsigned svalid[NWORDS];
    __shared__ unsigned ssup[NWORDS];
    __shared__ int slist[POST];
    unsigned long long* skey = (unsigned long long*)s_raw;
    unsigned short* spay = (unsigned short*)(s_raw + 16384);
    float4* sb = (float4*)s_raw;
    int b = blockIdx.x, t = threadIdx.x;
    if (t < NWORDS) { svalid[t] = 0; ssup[t] = 0; }
    for (int i = t; i < 2048; i += 1024) {
        unsigned long long kk = 0ull;
        if (i < NREAL) kk = g_ckey[b * KC + i];
        skey[i] = kk; spay[i] = (unsigned short)i;
    }
    for (int k2 = 2; k2 <= 2048; k2 <<= 1)
        for (int j = k2 >> 1; j > 0; j >>= 1) {
            __syncthreads();
            for (int i = t; i < 2048; i += 1024) {
                int ix = i ^ j;
                if (ix > i) {
                    bool up = ((i & k2) == 0);
                    unsigned long long a = skey[i], c = skey[ix];
                    if (up ? (a < c) : (a > c)) {
                        skey[i] = c; skey[ix] = a;
                        unsigned short tp = spay[i]; spay[i] = spay[ix]; spay[ix] = tp;
                    }
                }
            }
        }
    __syncthreads();
    unsigned long long kkA = skey[t], kkB = skey[t + 1024];
    unsigned short pyA = spay[t], pyB = spay[t + 1024];
    __syncthreads();
    #pragma unroll
    for (int half = 0; half < 2; half++) {
        int i = t + half * 1024;
        if (i >= KC) break;
        unsigned long long kk = half ? kkB : kkA;
        unsigned short py = half ? pyB : pyA;
        unsigned hi = (unsigned)(kk >> 32);
        if (hi > 0x80000000u) {
            int ci = b * KC + (int)py;
            float4 bxv = g_cbox4[ci];
            float off = (float)g_clabel[ci] * 1025.0f;
            float4 ob = make_float4(bxv.x + off, bxv.y + off, bxv.z + off, bxv.w + off);
            sb[i] = ob;
            sa[i] = (ob.z - ob.x) * (ob.w - ob.y);
            ssc[i] = g_cscore[ci];
            sslot[i] = py;
            atomicOr(&svalid[i >> 5], 1u << (i & 31));
        } else {
            sb[i] = make_float4(0.f, 0.f, 0.f, 0.f);
            sa[i] = 0.f; ssc[i] = 0.f; sslot[i] = 0;
        }
    }
    __syncthreads();
    int cnt = 0;
    for (int w = 0; w < NWORDS && cnt < POST; w++) {
        unsigned alive = svalid[w] & ~ssup[w];
        while (alive) {
            int bit = __ffs(alive) - 1;
            int i = (w << 5) + bit;
            if (t == 0) slist[cnt] = i;
            float4 bi = sb[i];
            float ai = sa[i];
            for (int j = i + 1 + t; j < KC; j += 1024) {
                float4 bj = sb[j];
                float iw = fminf(bi.z, bj.z) - fmaxf(bi.x, bj.x);
                float ih = fminf(bi.w, bj.w) - fmaxf(bi.y, bj.y);
                float inter = fmaxf(iw, 0.f) * fmaxf(ih, 0.f);
                float uni = fmaxf(ai + sa[j] - inter, 1e-9f);
                if (inter > 0.6f * uni) atomicOr(&ssup[j >> 5], 1u << (j & 31));
            }
            __syncthreads();
            cnt++;
            if (cnt >= POST) break;
            alive = svalid[w] & ~ssup[w] & (0xFFFFFFFEu << bit);
        }
    }
    __syncthreads();
    float* o5 = out + (size_t)b * POST * 5;
    float* ol = out + NBATCH * POST * 5 + b * POST;
    float* ov = out + NBATCH * POST * 5 + NBATCH * POST + b * POST;
    for (int k = t; k < POST; k += 1024) {
        float b0 = 0.f, b1 = 0.f, b2 = 0.f, b3 = 0.f, sc = 0.f, lab = 0.f, val = 0.f;
        if (k < cnt) {
            int i = slist[k];
            int ci = b * KC + (int)sslot[i];
            float4 bxv = g_cbox4[ci];
            b0 = bxv.x; b1 = bxv.y; b2 = bxv.z; b3 = bxv.w;
            sc = ssc[i];
            lab = (float)g_clabel[ci];
            val = 1.0f;
        }
        o5[k * 5 + 0] = b0; o5[k * 5 + 1] = b1;
        o5[k * 5 + 2] = b2; o5[k * 5 + 3] = b3;
        o5[k * 5 + 4] = sc;
        ol[k] = lab; ov[k] = val;
    }
}

// ---------------- launch ------------------------------------------------------
extern "C" void kernel_launch(void* const* d_in, const int* in_sizes, int n_in,
                              void* d_out, int out_size) {
    InPtrs P;
    bool sig_order = (n_in < 2) || (in_sizes[1] == 6400);
    for (int l = 0; l < 5; l++) {
        if (sig_order) {
            P.loc[l] = (const float*)d_in[l];
            P.cls[l] = (const float*)d_in[5 + l];
            P.box[l] = (const float*)d_in[10 + l];
            P.ctr[l] = (const float*)d_in[15 + l];
        } else {
            P.loc[l] = (const float*)d_in[4 * l + 0];
            P.cls[l] = (const float*)d_in[4 * l + 1];
            P.box[l] = (const float*)d_in[4 * l + 2];
            P.ctr[l] = (const float*)d_in[4 * l + 3];
        }
    }
    k_mega<<<NBLK_A, 256>>>(P);                 // 1: init..select, 4 grid barriers
    k_final<<<NBATCH, 1024>>>((float*)d_out);   // 2: sort+NMS+emit
}

// round 13
// speedup vs baseline: 1.1836x; 1.1836x over previous
#include <cuda_runtime.h>
#include <math.h>
#include <stdint.h>

// ---------------- problem constants (IMG 800x1024, strides 8..128) ----------
#define NBATCH 16
#define NCLS   80
#define TOPN   300
#define KC     1504          // padded candidates per image (5*300 = 1500 real)
#define NWORDS 47            // ceil(1504/32)
#define POST   100
#define CAP    4096          // survivor cap per (level,batch) pair

__constant__ int c_HW[5]   = {12800, 3200, 800, 208, 56};
__constant__ int c_CHW[5]  = {1024000, 256000, 64000, 16640, 4480};
__constant__ int c_LOFF[5] = {0, 204800, 256000, 268800, 272128};
__constant__ int c_R[5]    = {40, 80, 300, 300, 300};
__constant__ int c_BPP[5]  = {250, 63, 16, 5, 2};
__constant__ int c_BOFF[5] = {0, 4000, 5008, 5264, 5344};
#define NBLOCKS_COLLECT 5376
#define SCTR_TOTAL 273024

// ---------------- device scratch (static, allocation-free) ------------------
__device__ float    g_sctr[SCTR_TOTAL];      // exact sigmoid(ctr)
__device__ float    g_L[SCTR_TOTAL];         // per-position logit threshold
__device__ unsigned g_hist1[80 * 2048];
__device__ unsigned g_scnt[80];
__device__ unsigned long long g_surv[(size_t)80 * CAP];
__device__ float    g_cscore[NBATCH * KC];
__device__ float4   g_cbox4[NBATCH * KC];
__device__ int      g_clabel[NBATCH * KC];

struct InPtrs {
    const float* loc[5];
    const float* cls[5];
    const float* box[5];
    const float* ctr[5];
};

__device__ __forceinline__ unsigned fkey(float f) {
    unsigned b = __float_as_uint(f);
    return b ^ ((unsigned)((int)b >> 31) | 0x80000000u);
}
__device__ __forceinline__ float sigm(float x) { return 1.0f / (1.0f + expf(-x)); }

__device__ __forceinline__ float approx_rcp(float d) {
    float r = __int_as_float(0x7EF311C3 - __float_as_int(d));
    r = r * (2.0f - d * r);
    r = r * (2.0f - d * r);
    return r;
}
// MUFU-free approx sigmoid (sampling only), |rel err| <= ~0.25%
__device__ __forceinline__ float approx_a(float cv, float sv) {
    float t = fminf(cv, 60.0f) * -1.44269504f;
    float fl = floorf(t);
    float f = t - fl;
    float p2 = fmaf(fmaf(0.33718944f, f, 0.65763628f), f, 1.0017247f);
    float z = p2 * __int_as_float(((int)fl + 127) << 23);
    return approx_rcp(1.0f + z) * sv;
}

__device__ __forceinline__ void map_block(int bid, int& l, int& b, int& chunk) {
    if (bid < 4000)      l = 0;
    else if (bid < 5008) l = 1;
    else if (bid < 5264) l = 2;
    else if (bid < 5344) l = 3;
    else                 l = 4;
    int rel = bid - c_BOFF[l];
    b = rel / c_BPP[l];
    chunk = rel % c_BPP[l];
}

// ---------------- kernel 1: zero scratch + exact sigmoid(ctr) [R6-proven] ----
__global__ __launch_bounds__(256) void k_init(InPtrs P) {
    int i = blockIdx.x * 256 + threadIdx.x;
    if (i < 80 * 2048) g_hist1[i] = 0;
    if (i < 80) g_scnt[i] = 0;
    if (i < NBATCH * KC) g_cscore[i] = -1.0f;
    if (i < SCTR_TOTAL) {
        int l = (i < 204800) ? 0 : (i < 256000) ? 1 : (i < 268800) ? 2 : (i < 272128) ? 3 : 4;
        g_sctr[i] = sigm(P.ctr[l][i - c_LOFF[l]]);
    }
}

// ---------------- kernel 2: sampled approx-score histogram [R6-proven] -------
__global__ __launch_bounds__(256) void k_sample(InPtrs P) {
    __shared__ unsigned hist[2048];
    for (int i = threadIdx.x; i < 2048; i += 256) hist[i] = 0;
    __syncthreads();
    int bid = blockIdx.x;
    int l, b, sub, nsub, stride;
    if (bid < 128)      { l = 0; b = bid >> 3; sub = bid & 7; nsub = 8; stride = 32; }
    else if (bid < 160) { l = 1; b = (bid - 128) >> 1; sub = (bid - 128) & 1; nsub = 2; stride = 8; }
    else if (bid < 176) { l = 2; b = bid - 160; sub = 0; nsub = 1; stride = 1; }
    else if (bid < 192) { l = 3; b = bid - 176; sub = 0; nsub = 1; stride = 1; }
    else                { l = 4; b = bid - 192; sub = 0; nsub = 1; stride = 1; }
    int chw4 = c_CHW[l] >> 2;
    int per = chw4 / nsub;
    int hw = c_HW[l];
    const float4* cls4 = (const float4*)(P.cls[l]) + (size_t)b * chw4 + (size_t)sub * per;
    const float4* sctr4 = (const float4*)(g_sctr + c_LOFF[l] + b * hw);
    int base_e = sub * per * 4;
    for (int i4 = threadIdx.x * stride; i4 < per; i4 += 256 * stride) {
        float4 v = cls4[i4];
        int e = base_e + (i4 << 2);
        int pos0 = e % hw;
        float4 s4 = sctr4[pos0 >> 2];
        float vv[4] = {v.x, v.y, v.z, v.w};
        float ss[4] = {s4.x, s4.y, s4.z, s4.w};
        #pragma unroll
        for (int k = 0; k < 4; k++) {
            float cv = vv[k];
            if (cv < -2.945f) continue;
            float a = approx_a(cv, ss[k]);
            atomicAdd(&hist[min(2047, (int)(a * 2048.0f))], 1u);
        }
    }
    __syncthreads();
    int p = l * 16 + b;
    for (int i = threadIdx.x; i < 2048; i += 256)
        if (hist[i]) atomicAdd(&g_hist1[p * 2048 + i], hist[i]);
}

// ---------------- kernel 3: threshold -> per-position logit L [R6-proven] ----
__global__ __launch_bounds__(256) void k_threshL() {
    __shared__ unsigned sh[2048];
    __shared__ unsigned part[256];
    __shared__ float s_thr;
    int p = blockIdx.x, t = threadIdx.x;
    if (t == 0) s_thr = 0.0f;
    unsigned R = (unsigned)c_R[p / 16];
    const unsigned* h = g_hist1 + (size_t)p * 2048;
    unsigned lsum = 0;
    for (int i = 0; i < 8; i++) { unsigned v = h[t * 8 + i]; sh[t * 8 + i] = v; lsum += v; }
    part[t] = lsum;
    __syncthreads();
    for (int off = 1; off < 256; off <<= 1) {
        unsigned o = (t + off < 256) ? part[t + off] : 0u;
        __syncthreads();
        part[t] += o;
        __syncthreads();
    }
    unsigned cum = (t < 255) ? part[t + 1] : 0u;
    for (int i = 7; i >= 0; i--) {
        int bidx = t * 8 + i;
        unsigned hv = sh[bidx];
        if (cum < R && cum + hv >= R)
            s_thr = (float)bidx * (1.0f / 2048.0f) * 0.985f;
        cum += hv;
    }
    __syncthreads();
    float thr = s_thr;
    int l = p / 16, b = p % 16;
    int hw = c_HW[l];
    int base = c_LOFF[l] + b * hw;
    for (int i = t; i < hw; i += 256) {
        float sv = g_sctr[base + i];
        float L;
        if (thr <= 0.0f) L = -2.944f;
        else {
            float x = thr / sv;
            if (x >= 1.0f) L = 1e30f;
            else L = fmaxf(logf(x / (1.0f - x)) - 0.02f, -2.944f);
        }
        g_L[base + i] = L;
    }
}

// ---------------- kernel 4: full sweep [R6-proven float4 body] ---------------
template <int HW>
__device__ __forceinline__ void collect_body(const float4* cls4, const float4* Lv,
                                             const float* sctr, int start, int chw, int p) {
    int e4end = min(start + 4096, chw) >> 2;
    for (int e4 = (start >> 2) + threadIdx.x; e4 < e4end; e4 += 256) {
        float4 v = cls4[e4];
        int e = e4 << 2;
        int c0 = e / HW;
        int pos0 = e - c0 * HW;
        float4 L4 = Lv[pos0 >> 2];
        float vv[4] = {v.x, v.y, v.z, v.w};
        float LL[4] = {L4.x, L4.y, L4.z, L4.w};
        #pragma unroll
        for (int k = 0; k < 4; k++) {
            float cv = vv[k];
            if (cv < LL[k]) continue;
            float se = sigm(cv);              // exact path, rare
            if (se <= 0.05f) continue;
            float sv = sctr[pos0 + k];
            float m = se * sv;
            unsigned key32 = __float_as_uint(m) | 0x80000000u;
            unsigned idx = (unsigned)((pos0 + k) * NCLS + c0);
            unsigned long long key = ((unsigned long long)key32 << 32) | (unsigned)(~idx);
            unsigned slot = atomicAdd(&g_scnt[p], 1u);
            if (slot < CAP) g_surv[(size_t)p * CAP + slot] = key;
        }
    }
}

__global__ __launch_bounds__(256) void k_collect(InPtrs P) {
    int l, b, chunk; map_block(blockIdx.x, l, b, chunk);
    int p = l * 16 + b;
    int start = chunk * 4096;
    switch (l) {
    case 0: collect_body<12800>((const float4*)(P.cls[0] + (size_t)b * 1024000),
            (const float4*)(g_L + 0 + b * 12800), g_sctr + 0 + b * 12800, start, 1024000, p); break;
    case 1: collect_body<3200>((const float4*)(P.cls[1] + (size_t)b * 256000),
            (const float4*)(g_L + 204800 + b * 3200), g_sctr + 204800 + b * 3200, start, 256000, p); break;
    case 2: collect_body<800>((const float4*)(P.cls[2] + (size_t)b * 64000),
            (const float4*)(g_L + 256000 + b * 800), g_sctr + 256000 + b * 800, start, 64000, p); break;
    case 3: collect_body<208>((const float4*)(P.cls[3] + (size_t)b * 16640),
            (const float4*)(g_L + 268800 + b * 208), g_sctr + 268800 + b * 208, start, 16640, p); break;
    case 4: collect_body<56>((const float4*)(P.cls[4] + (size_t)b * 4480),
            (const float4*)(g_L + 272128 + b * 56), g_sctr + 272128 + b * 56, start, 4480, p); break;
    }
}

// monotone 1024-bin key for score-prune (hi in [0x80000000, 0xBF800000])
__device__ __forceinline__ int keybin(unsigned hi) {
    int d = (int)(hi - 0xBD000000u);
    d >>= 16;
    return min(1023, max(d, 0));
}

// ---------------- kernel 5: exact per-pair top-300 [R6-proven] ---------------
__global__ __launch_bounds__(512) void k_select(InPtrs P) {
    __shared__ unsigned long long sk[CAP];
    __shared__ unsigned hist[1024];
    __shared__ unsigned part[512];
    __shared__ int s_cnt2;
    __shared__ int s_B;
    int p = blockIdx.x, t = threadIdx.x;
    int l = p / 16, b = p % 16;
    int n = min((int)g_scnt[p], CAP);
    const unsigned long long* sv = g_surv + (size_t)p * CAP;
    int m = n;
    bool pruned = false;
    if (n > 1024) {
        for (int i = t; i < 1024; i += 512) hist[i] = 0;
        if (t == 0) { s_cnt2 = 0; s_B = 0; }
        __syncthreads();
        for (int i = t; i < n; i += 512)
            atomicAdd(&hist[keybin((unsigned)(sv[i] >> 32))], 1u);
        __syncthreads();
        unsigned lsum = hist[2 * t] + hist[2 * t + 1];
        part[t] = lsum;
        __syncthreads();
        for (int off = 1; off < 512; off <<= 1) {
            unsigned o = (t + off < 512) ? part[t + off] : 0u;
            __syncthreads();
            part[t] += o;
            __syncthreads();
        }
        unsigned cum = (t < 511) ? part[t + 1] : 0u;
        unsigned h1 = hist[2 * t + 1], h0 = hist[2 * t];
        if (cum < 300u && cum + h1 >= 300u) s_B = 2 * t + 1;
        cum += h1;
        if (cum < 300u && cum + h0 >= 300u) s_B = 2 * t;
        __syncthreads();
        int B = s_B;
        for (int i = t; i < n; i += 512) {
            unsigned long long key = sv[i];
            if (keybin((unsigned)(key >> 32)) >= B) {
                int idx = atomicAdd(&s_cnt2, 1);
                if (idx < CAP) sk[idx] = key;
            }
        }
        __syncthreads();
        if (s_cnt2 <= 1024) { m = s_cnt2; pruned = true; }
    }
    int P2 = 512; while (P2 < m) P2 <<= 1;
    for (int i = t; i < P2; i += 512) {
        if (i < m) { if (!pruned) sk[i] = sv[i]; }
        else sk[i] = 0ull;
    }
    __syncthreads();
    for (int k2 = 2; k2 <= P2; k2 <<= 1)
        for (int j = k2 >> 1; j > 0; j >>= 1) {
            for (int i = t; i < P2; i += 512) {
                int ix = i ^ j;
                if (ix > i) {
                    bool up = ((i & k2) == 0);
                    unsigned long long a = sk[i], c = sk[ix];
                    if (up ? (a < c) : (a > c)) { sk[i] = c; sk[ix] = a; }
                }
            }
            __syncthreads();
        }
    if (t < TOPN) {
        int ci = b * KC + l * TOPN + t;
        bool valid = false;
        if (t < m) {
            unsigned long long key = sk[t];
            unsigned hi = (unsigned)(key >> 32);
            if (hi > 0x80000000u) {
                valid = true;
                float sc = __uint_as_float(hi ^ 0x80000000u);
                unsigned idx = ~(unsigned)(key & 0xFFFFFFFFu);
                int pos = (int)(idx / NCLS), c = (int)(idx % NCLS);
                int hw = c_HW[l];
                const float* bx = P.box[l] + (size_t)b * 4 * hw;
                float bl = bx[pos], bt = bx[hw + pos], br = bx[2 * hw + pos], bbo = bx[3 * hw + pos];
                float lx = P.loc[l][2 * pos], ly = P.loc[l][2 * pos + 1];
                float x1 = fminf(fmaxf(lx - bl, 0.f), 1023.f);
                float y1 = fminf(fmaxf(ly - bt, 0.f), 799.f);
                float x2 = fminf(fmaxf(lx + br, 0.f), 1023.f);
                float y2 = fminf(fmaxf(ly + bbo, 0.f), 799.f);
                g_cscore[ci] = sqrtf(fmaxf(sc, 1e-12f));
                g_cbox4[ci] = make_float4(x1, y1, x2, y2);
                g_clabel[ci] = c + 1;
            }
        }
        if (!valid) g_cscore[ci] = -1.0f;   // replay-safe sentinel
    }
}

// ---------------- kernel 6: sort + CHUNKED warp-serial NMS + emit ------------
__global__ __launch_bounds__(1024) void k_final(float* out) {
    __shared__ __align__(16) unsigned char s_raw[24064];   // skey(16KB) | sb(23.5KB)
    __shared__ float sa[KC];
    __shared__ float ssc[KC];
    __shared__ unsigned short sslot[KC];
    __shared__ unsigned svalid[NWORDS];
    __shared__ unsigned ssup[NWORDS];
    __shared__ int slist[POST];
    __shared__ int s_cnt;
    __shared__ unsigned s_kept;
    unsigned long long* skey = (unsigned long long*)s_raw;
    float4* sb = (float4*)s_raw;
    int b = blockIdx.x, t = threadIdx.x;
    if (t < NWORDS) { svalid[t] = 0; ssup[t] = 0; }
    if (t == 0) s_cnt = 0;
    // phase 1: keys (score desc, slot asc via ~slot) + bitonic sort [R6-proven]
    for (int i = t; i < 2048; i += 1024) {
        unsigned long long kk = 0ull;
        if (i < KC) {
            float sc = g_cscore[b * KC + i];
            kk = ((unsigned long long)fkey(sc) << 32) | (unsigned)(~(unsigned)i);
        }
        skey[i] = kk;
    }
    for (int k2 = 2; k2 <= 2048; k2 <<= 1)
        for (int j = k2 >> 1; j > 0; j >>= 1) {
            __syncthreads();
            for (int i = t; i < 2048; i += 1024) {
                int ix = i ^ j;
                if (ix > i) {
                    bool up = ((i & k2) == 0);
                    unsigned long long a = skey[i], c = skey[ix];
                    if (up ? (a < c) : (a > c)) { skey[i] = c; skey[ix] = a; }
                }
            }
        }
    __syncthreads();
    // phase 2: decode into sb/sa/ssc/sslot (sb overlays skey)  [R6-proven]
    unsigned long long kkA = skey[t];
    unsigned long long kkB = (t + 1024 < 2048) ? skey[t + 1024] : 0ull;
    __syncthreads();
    #pragma unroll
    for (int half = 0; half < 2; half++) {
        int i = t + half * 1024;
        if (i >= KC) break;
        unsigned long long kk = half ? kkB : kkA;
        unsigned hi = (unsigned)(kk >> 32);
        if (hi > 0x80000000u) {
            int slot = (int)(~(unsigned)(kk & 0xFFFFFFFFu));
            int ci = b * KC + slot;
            float4 bx = g_cbox4[ci];
            float off = (float)g_clabel[ci] * 1025.0f;
            float4 ob = make_float4(bx.x + off, bx.y + off, bx.z + off, bx.w + off);
            sb[i] = ob;
            sa[i] = (ob.z - ob.x) * (ob.w - ob.y);
            ssc[i] = __uint_as_float(hi ^ 0x80000000u);
            sslot[i] = (unsigned short)slot;
            atomicOr(&svalid[i >> 5], 1u << (i & 31));
        } else {
            sb[i] = make_float4(0.f, 0.f, 0.f, 0.f);
            sa[i] = 0.f; ssc[i] = -1e30f; sslot[i] = 0;
        }
    }
    __syncthreads();
    // phase 3: chunked NMS — warp 0 serial within 32-word, block applies forward
    for (int w = 0; w < NWORDS; w++) {
        if (t < 32) {
            int i = (w << 5) + t;
            float4 bi = sb[i];
            float ai = sa[i];
            unsigned alive = svalid[w] & ~ssup[w];
            unsigned kept = 0;
            int cnt = s_cnt;
            while (alive && cnt < POST) {
                int bit = __ffs(alive) - 1;
                float bx_ = __shfl_sync(0xffffffffu, bi.x, bit);
                float by_ = __shfl_sync(0xffffffffu, bi.y, bit);
                float bz_ = __shfl_sync(0xffffffffu, bi.z, bit);
                float bw_ = __shfl_sync(0xffffffffu, bi.w, bit);
                float aa_ = __shfl_sync(0xffffffffu, ai, bit);
                float iw = fminf(bi.z, bz_) - fmaxf(bi.x, bx_);
                float ih = fminf(bi.w, bw_) - fmaxf(bi.y, by_);
                float inter = fmaxf(iw, 0.f) * fmaxf(ih, 0.f);
                float uni = fmaxf(ai + aa_ - inter, 1e-9f);
                bool sup = (inter > 0.6f * uni) && (t > bit);
                unsigned supm = __ballot_sync(0xffffffffu, sup);
                alive &= ~supm & ~(1u << bit);
                if (t == 0) slist[cnt] = i - t + bit;   // (w<<5)+bit
                kept |= 1u << bit;
                cnt++;
            }
            if (t == 0) { s_cnt = cnt; s_kept = kept; }
        }
        __syncthreads();
        int cnt = s_cnt;
        unsigned kept = s_kept;
        bool last = (cnt >= POST) || (w == NWORDS - 1);
        if (kept && !last) {
            // apply this word's kept-set to all later candidates
            for (int j = ((w + 1) << 5) + t; j < KC; j += 1024) {
                float4 bj = sb[j];
                float aj = sa[j];
                bool sup = false;
                unsigned kb = kept;
                while (kb) {
                    int bit = __ffs(kb) - 1; kb &= kb - 1;
                    int k = (w << 5) + bit;
                    float4 bk = sb[k];          // broadcast LDS
                    float iw = fminf(bj.z, bk.z) - fmaxf(bj.x, bk.x);
                    float ih = fminf(bj.w, bk.w) - fmaxf(bj.y, bk.y);
                    float inter = fmaxf(iw, 0.f) * fmaxf(ih, 0.f);
                    float uni = fmaxf(aj + sa[k] - inter, 1e-9f);
                    sup |= inter > 0.6f * uni;
                }
                unsigned m = __ballot_sync(0xffffffffu, sup);   // warp = one word
                if ((t & 31) == 0 && m) atomicOr(&ssup[j >> 5], m);
            }
        }
        __syncthreads();
        if (last && cnt >= POST) break;
    }
    __syncthreads();
    // phase 4: emit
    int cnt = s_cnt;
    float* o5 = out + (size_t)b * POST * 5;
    float* ol = out + NBATCH * POST * 5 + b * POST;
    float* ov = out + NBATCH * POST * 5 + NBATCH * POST + b * POST;
    for (int k = t; k < POST; k += 1024) {
        float b0 = 0.f, b1 = 0.f, b2 = 0.f, b3 = 0.f, sc = 0.f, lab = 0.f, val = 0.f;
        if (k < cnt) {
            int i = slist[k];
            int ci = b * KC + (int)sslot[i];
            float4 bx = g_cbox4[ci];
            b0 = bx.x; b1 = bx.y; b2 = bx.z; b3 = bx.w;
            sc = ssc[i];
            lab = (float)g_clabel[ci];
            val = 1.0f;
        }
        o5[k * 5 + 0] = b0; o5[k * 5 + 1] = b1;
        o5[k * 5 + 2] = b2; o5[k * 5 + 3] = b3;
        o5[k * 5 + 4] = sc;
        ol[k] = lab; ov[k] = val;
    }
}

// ---------------- launch ------------------------------------------------------
extern "C" void kernel_launch(void* const* d_in, const int* in_sizes, int n_in,
                              void* d_out, int out_size) {
    InPtrs P;
    bool sig_order = (n_in < 2) || (in_sizes[1] == 6400);
    for (int l = 0; l < 5; l++) {
        if (sig_order) {
            P.loc[l] = (const float*)d_in[l];
            P.cls[l] = (const float*)d_in[5 + l];
            P.box[l] = (const float*)d_in[10 + l];
            P.ctr[l] = (const float*)d_in[15 + l];
        } else {
            P.loc[l] = (const float*)d_in[4 * l + 0];
            P.cls[l] = (const float*)d_in[4 * l + 1];
            P.box[l] = (const float*)d_in[4 * l + 2];
            P.ctr[l] = (const float*)d_in[4 * l + 3];
        }
    }
    k_init<<<(SCTR_TOTAL + 255) / 256, 256>>>(P);   // 1: zero + sctr
    k_sample<<<208, 256>>>(P);                      // 2: sampled hist
    k_threshL<<<80, 256>>>();                       // 3: threshold -> logit L
    k_collect<<<NBLOCKS_COLLECT, 256>>>(P);         // 4: R6 sweep
    k_select<<<80, 512>>>(P);                       // 5: R6 top-300
    k_final<<<NBATCH, 1024>>>((float*)d_out);       // 6: sort + chunked NMS + emit
}